// round 1
// baseline (speedup 1.0000x reference)
#include <cuda_runtime.h>
#include <cstdint>

#define N_NODES_C 50000
#define N_PAIRS_C 800000
#define NHEADS_C 4
#define HEAD_DIM_C 64
#define NF_C 256   // NHEADS*HEAD_DIM

// scratch for projected q,k,v (allocation-free rule: __device__ globals)
__device__ float g_q[N_NODES_C * NF_C];
__device__ float g_k[N_NODES_C * NF_C];
__device__ float g_v[N_NODES_C * NF_C];

// ---------------------------------------------------------------------------
// packed f32x2 helpers
// ---------------------------------------------------------------------------
__device__ __forceinline__ void fma2(unsigned long long& d, unsigned long long a,
                                     unsigned long long b) {
    asm("fma.rn.f32x2 %0, %1, %2, %0;" : "+l"(d) : "l"(a), "l"(b));
}
__device__ __forceinline__ unsigned long long bcast2(float w) {
    unsigned long long r;
    asm("mov.b64 %0, {%1, %1};" : "=l"(r) : "f"(w));
    return r;
}
__device__ __forceinline__ void unpack2(unsigned long long u, float& lo, float& hi) {
    asm("mov.b64 {%0, %1}, %2;" : "=f"(lo), "=f"(hi) : "l"(u));
}

union F4U2 { float4 f4; unsigned long long u2[2]; };

// ---------------------------------------------------------------------------
// Kernel 1: per-head projections q,k,v.  One block = 64 nodes x 1 head.
// smem: sW[3][64][65] (padded, conflict-free) + sX[64][68] transposed [d][node]
// thread (e = tid%64, g = tid/64) computes dims e for nodes g*16..g*16+15,
// node-pairs packed into fma.rn.f32x2.
// ---------------------------------------------------------------------------
#define TILE_N 64
#define PROJ_THREADS 256
#define SW_PITCH 65
#define SX_PITCH 68
#define SW_MAT (64 * SW_PITCH)
#define SMEM_FLOATS (3 * SW_MAT + 64 * SX_PITCH)

__global__ void __launch_bounds__(PROJ_THREADS)
proj_kernel(const float* __restrict__ x,
            const float* __restrict__ Wq,
            const float* __restrict__ Wk,
            const float* __restrict__ Wv) {
    extern __shared__ float sm[];
    float* sW = sm;                    // 3 * 64 * 65
    float* sX = sm + 3 * SW_MAT;       // 64 * 68  (sX[d*68 + node_local])

    const int h   = blockIdx.y;
    const int n0  = blockIdx.x * TILE_N;
    const int tid = threadIdx.x;

    // load weights for this head: W[h, e, d] row-major
    for (int idx = tid; idx < 3 * 64 * 64; idx += PROJ_THREADS) {
        int m = idx >> 12;            // matrix 0..2
        int r = idx & 4095;
        int e = r >> 6, d = r & 63;
        const float* W = (m == 0) ? Wq : ((m == 1) ? Wk : Wv);
        sW[m * SW_MAT + e * SW_PITCH + d] = W[h * 4096 + e * 64 + d];
    }
    // load x tile transposed: sX[d][node]
    for (int idx = tid; idx < TILE_N * 64; idx += PROJ_THREADS) {
        int nl = idx >> 6, d = idx & 63;
        int n = n0 + nl;
        float v = (n < N_NODES_C) ? x[(size_t)n * NF_C + h * HEAD_DIM_C + d] : 0.0f;
        sX[d * SX_PITCH + nl] = v;
    }
    __syncthreads();

    const int e = tid & 63;
    const int g = tid >> 6;           // 0..3, node group of 16

    const float* wqr = sW + 0 * SW_MAT + e * SW_PITCH;
    const float* wkr = sW + 1 * SW_MAT + e * SW_PITCH;
    const float* wvr = sW + 2 * SW_MAT + e * SW_PITCH;

    unsigned long long aq[8], ak[8], av[8];
#pragma unroll
    for (int p = 0; p < 8; p++) { aq[p] = 0ULL; ak[p] = 0ULL; av[p] = 0ULL; }

#pragma unroll 4
    for (int kk = 0; kk < 64; kk++) {
        unsigned long long bq = bcast2(wqr[kk]);
        unsigned long long bk = bcast2(wkr[kk]);
        unsigned long long bv = bcast2(wvr[kk]);
        const float4* xp = (const float4*)(sX + kk * SX_PITCH + g * 16);
        F4U2 x0, x1, x2, x3;
        x0.f4 = xp[0]; x1.f4 = xp[1]; x2.f4 = xp[2]; x3.f4 = xp[3];
        unsigned long long xu[8] = {x0.u2[0], x0.u2[1], x1.u2[0], x1.u2[1],
                                    x2.u2[0], x2.u2[1], x3.u2[0], x3.u2[1]};
#pragma unroll
        for (int p = 0; p < 8; p++) {
            fma2(aq[p], xu[p], bq);
            fma2(ak[p], xu[p], bk);
            fma2(av[p], xu[p], bv);
        }
    }

    // store: q[n, h, e] etc
#pragma unroll
    for (int p = 0; p < 8; p++) {
        float qlo, qhi, klo, khi, vlo, vhi;
        unpack2(aq[p], qlo, qhi);
        unpack2(ak[p], klo, khi);
        unpack2(av[p], vlo, vhi);
        int nl = g * 16 + 2 * p;
        int n  = n0 + nl;
        if (n < N_NODES_C) {
            size_t o = (size_t)n * NF_C + h * HEAD_DIM_C + e;
            g_q[o] = qlo; g_k[o] = klo; g_v[o] = vlo;
        }
        if (n + 1 < N_NODES_C) {
            size_t o = (size_t)(n + 1) * NF_C + h * HEAD_DIM_C + e;
            g_q[o] = qhi; g_k[o] = khi; g_v[o] = vhi;
        }
    }
}

// ---------------------------------------------------------------------------
// Kernel 2: one warp per edge.  Lane owns 8 consecutive dims (head = lane/8).
// alpha_h = (sum_d q[i]*w*k[j]) * 0.125 * phi;  y[i] += alpha_h * v[j]
// scatter via red.global.add.v4.f32 (2 per lane).
// ---------------------------------------------------------------------------
__global__ void __launch_bounds__(256)
edge_kernel(const float* __restrict__ w_ij,
            const int* __restrict__ idx_i,
            const int* __restrict__ idx_j,
            const float* __restrict__ phi,
            float* __restrict__ y) {
    int eid  = (blockIdx.x * blockDim.x + threadIdx.x) >> 5;
    int lane = threadIdx.x & 31;
    if (eid >= N_PAIRS_C) return;

    int   i  = idx_i[eid];
    int   j  = idx_j[eid];
    float ph = phi[eid];

    int off = lane * 8;
    const float4* qp = (const float4*)(g_q  + (size_t)i  * NF_C + off);
    const float4* kp = (const float4*)(g_k  + (size_t)j  * NF_C + off);
    const float4* vp = (const float4*)(g_v  + (size_t)j  * NF_C + off);
    const float4* wp = (const float4*)(w_ij + (size_t)eid * NF_C + off);

    float4 q0 = qp[0], q1 = qp[1];
    float4 w0 = wp[0], w1 = wp[1];
    float4 k0 = kp[0], k1 = kp[1];

    float s = q0.x * w0.x * k0.x + q0.y * w0.y * k0.y
            + q0.z * w0.z * k0.z + q0.w * w0.w * k0.w
            + q1.x * w1.x * k1.x + q1.y * w1.y * k1.y
            + q1.z * w1.z * k1.z + q1.w * w1.w * k1.w;

    // reduce within 8-lane head segment
    s += __shfl_xor_sync(0xffffffffu, s, 1);
    s += __shfl_xor_sync(0xffffffffu, s, 2);
    s += __shfl_xor_sync(0xffffffffu, s, 4);

    float alpha = s * 0.125f * ph;   // 1/sqrt(64) = 0.125

    float4 v0 = vp[0], v1 = vp[1];
    float* yp = y + (size_t)i * NF_C + off;

    asm volatile("red.global.add.v4.f32 [%0], {%1, %2, %3, %4};"
                 :: "l"(yp), "f"(alpha * v0.x), "f"(alpha * v0.y),
                    "f"(alpha * v0.z), "f"(alpha * v0.w) : "memory");
    asm volatile("red.global.add.v4.f32 [%0], {%1, %2, %3, %4};"
                 :: "l"(yp + 4), "f"(alpha * v1.x), "f"(alpha * v1.y),
                    "f"(alpha * v1.z), "f"(alpha * v1.w) : "memory");
}

// ---------------------------------------------------------------------------
// launch
// ---------------------------------------------------------------------------
extern "C" void kernel_launch(void* const* d_in, const int* in_sizes, int n_in,
                              void* d_out, int out_size) {
    const float* x     = (const float*)d_in[0];
    const float* w_ij  = (const float*)d_in[1];
    const int*   idx_i = (const int*)d_in[2];
    const int*   idx_j = (const int*)d_in[3];
    const float* phi   = (const float*)d_in[4];
    const float* Wq    = (const float*)d_in[5];
    const float* Wk    = (const float*)d_in[6];
    const float* Wv    = (const float*)d_in[7];
    float* y = (float*)d_out;

    // output is poisoned; zero it (graph-capturable async memset)
    cudaMemsetAsync(y, 0, (size_t)N_NODES_C * NF_C * sizeof(float), 0);

    static const size_t smem_bytes = SMEM_FLOATS * sizeof(float);
    cudaFuncSetAttribute(proj_kernel, cudaFuncAttributeMaxDynamicSharedMemorySize,
                         (int)smem_bytes);

    dim3 pgrid((N_NODES_C + TILE_N - 1) / TILE_N, NHEADS_C);
    proj_kernel<<<pgrid, PROJ_THREADS, smem_bytes>>>(x, Wq, Wk, Wv);

    int warps_per_block = 256 / 32;
    int nblocks = (N_PAIRS_C + warps_per_block - 1) / warps_per_block;
    edge_kernel<<<nblocks, 256>>>(w_ij, idx_i, idx_j, phi, y);
}

// round 2
// speedup vs baseline: 1.2732x; 1.2732x over previous
#include <cuda_runtime.h>
#include <cuda_fp16.h>
#include <cstdint>

#define N_NODES_C 50000
#define N_PAIRS_C 800000
#define NHEADS_C 4
#define HEAD_DIM_C 64
#define NF_C 256   // NHEADS*HEAD_DIM

// scratch for projected q,k,v in fp16 (allocation-free rule: __device__ globals)
// 3 x 50000 x 256 x 2B = 76.8 MB total -> fits in L2 (126 MB)
__device__ __half g_q[N_NODES_C * NF_C];
__device__ __half g_k[N_NODES_C * NF_C];
__device__ __half g_v[N_NODES_C * NF_C];

// ---------------------------------------------------------------------------
// packed f32x2 helpers
// ---------------------------------------------------------------------------
__device__ __forceinline__ void fma2(unsigned long long& d, unsigned long long a,
                                     unsigned long long b) {
    asm("fma.rn.f32x2 %0, %1, %2, %0;" : "+l"(d) : "l"(a), "l"(b));
}
__device__ __forceinline__ unsigned long long bcast2(float w) {
    unsigned long long r;
    asm("mov.b64 %0, {%1, %1};" : "=l"(r) : "f"(w));
    return r;
}
__device__ __forceinline__ void unpack2(unsigned long long u, float& lo, float& hi) {
    asm("mov.b64 {%0, %1}, %2;" : "=f"(lo), "=f"(hi) : "l"(u));
}

union F4U2 { float4 f4; unsigned long long u2[2]; };

// ---------------------------------------------------------------------------
// Kernel 1: per-head projections q,k,v (fp32 compute, fp16 store).
// One block = 64 nodes x 1 head.
// ---------------------------------------------------------------------------
#define TILE_N 64
#define PROJ_THREADS 256
#define SW_PITCH 65
#define SX_PITCH 68
#define SW_MAT (64 * SW_PITCH)
#define SMEM_FLOATS (3 * SW_MAT + 64 * SX_PITCH)

__global__ void __launch_bounds__(PROJ_THREADS)
proj_kernel(const float* __restrict__ x,
            const float* __restrict__ Wq,
            const float* __restrict__ Wk,
            const float* __restrict__ Wv) {
    extern __shared__ float sm[];
    float* sW = sm;                    // 3 * 64 * 65
    float* sX = sm + 3 * SW_MAT;       // 64 * 68  (sX[d*68 + node_local])

    const int h   = blockIdx.y;
    const int n0  = blockIdx.x * TILE_N;
    const int tid = threadIdx.x;

    for (int idx = tid; idx < 3 * 64 * 64; idx += PROJ_THREADS) {
        int m = idx >> 12;
        int r = idx & 4095;
        int e = r >> 6, d = r & 63;
        const float* W = (m == 0) ? Wq : ((m == 1) ? Wk : Wv);
        sW[m * SW_MAT + e * SW_PITCH + d] = W[h * 4096 + e * 64 + d];
    }
    for (int idx = tid; idx < TILE_N * 64; idx += PROJ_THREADS) {
        int nl = idx >> 6, d = idx & 63;
        int n = n0 + nl;
        float v = (n < N_NODES_C) ? x[(size_t)n * NF_C + h * HEAD_DIM_C + d] : 0.0f;
        sX[d * SX_PITCH + nl] = v;
    }
    __syncthreads();

    const int e = tid & 63;
    const int g = tid >> 6;           // 0..3, node group of 16

    const float* wqr = sW + 0 * SW_MAT + e * SW_PITCH;
    const float* wkr = sW + 1 * SW_MAT + e * SW_PITCH;
    const float* wvr = sW + 2 * SW_MAT + e * SW_PITCH;

    unsigned long long aq[8], ak[8], av[8];
#pragma unroll
    for (int p = 0; p < 8; p++) { aq[p] = 0ULL; ak[p] = 0ULL; av[p] = 0ULL; }

#pragma unroll 4
    for (int kk = 0; kk < 64; kk++) {
        unsigned long long bq = bcast2(wqr[kk]);
        unsigned long long bk = bcast2(wkr[kk]);
        unsigned long long bv = bcast2(wvr[kk]);
        const float4* xp = (const float4*)(sX + kk * SX_PITCH + g * 16);
        F4U2 x0, x1, x2, x3;
        x0.f4 = xp[0]; x1.f4 = xp[1]; x2.f4 = xp[2]; x3.f4 = xp[3];
        unsigned long long xu[8] = {x0.u2[0], x0.u2[1], x1.u2[0], x1.u2[1],
                                    x2.u2[0], x2.u2[1], x3.u2[0], x3.u2[1]};
#pragma unroll
        for (int p = 0; p < 8; p++) {
            fma2(aq[p], xu[p], bq);
            fma2(ak[p], xu[p], bk);
            fma2(av[p], xu[p], bv);
        }
    }

    // store as fp16: q[n, h, e] etc
#pragma unroll
    for (int p = 0; p < 8; p++) {
        float qlo, qhi, klo, khi, vlo, vhi;
        unpack2(aq[p], qlo, qhi);
        unpack2(ak[p], klo, khi);
        unpack2(av[p], vlo, vhi);
        int nl = g * 16 + 2 * p;
        int n  = n0 + nl;
        if (n < N_NODES_C) {
            size_t o = (size_t)n * NF_C + h * HEAD_DIM_C + e;
            g_q[o] = __float2half_rn(qlo);
            g_k[o] = __float2half_rn(klo);
            g_v[o] = __float2half_rn(vlo);
        }
        if (n + 1 < N_NODES_C) {
            size_t o = (size_t)(n + 1) * NF_C + h * HEAD_DIM_C + e;
            g_q[o] = __float2half_rn(qhi);
            g_k[o] = __float2half_rn(khi);
            g_v[o] = __float2half_rn(vhi);
        }
    }
}

// ---------------------------------------------------------------------------
// Kernel 2: one warp per edge.  Lane owns 8 dims (head = lane/8).
// fp16 gathers (one 16B load per table per lane), fp32 w_ij streamed with
// __ldcs (evict-first) so q/k/v tables stay L2-resident.
// ---------------------------------------------------------------------------
__device__ __forceinline__ float dot8_h(uint4 qu, uint4 ku, float4 w0, float4 w1) {
    const __half2* q2 = (const __half2*)&qu;
    const __half2* k2 = (const __half2*)&ku;
    float2 qf0 = __half22float2(q2[0]);
    float2 qf1 = __half22float2(q2[1]);
    float2 qf2 = __half22float2(q2[2]);
    float2 qf3 = __half22float2(q2[3]);
    float2 kf0 = __half22float2(k2[0]);
    float2 kf1 = __half22float2(k2[1]);
    float2 kf2 = __half22float2(k2[2]);
    float2 kf3 = __half22float2(k2[3]);
    float s;
    s  = qf0.x * w0.x * kf0.x;
    s += qf0.y * w0.y * kf0.y;
    s += qf1.x * w0.z * kf1.x;
    s += qf1.y * w0.w * kf1.y;
    s += qf2.x * w1.x * kf2.x;
    s += qf2.y * w1.y * kf2.y;
    s += qf3.x * w1.z * kf3.x;
    s += qf3.y * w1.w * kf3.y;
    return s;
}

__global__ void __launch_bounds__(256)
edge_kernel(const float* __restrict__ w_ij,
            const int* __restrict__ idx_i,
            const int* __restrict__ idx_j,
            const float* __restrict__ phi,
            float* __restrict__ y) {
    int eid  = (blockIdx.x * blockDim.x + threadIdx.x) >> 5;
    int lane = threadIdx.x & 31;
    if (eid >= N_PAIRS_C) return;

    int   i  = idx_i[eid];
    int   j  = idx_j[eid];
    float ph = phi[eid];

    int off = lane * 8;
    const uint4*  qp = (const uint4*)(g_q + (size_t)i * NF_C + off);
    const uint4*  kp = (const uint4*)(g_k + (size_t)j * NF_C + off);
    const uint4*  vp = (const uint4*)(g_v + (size_t)j * NF_C + off);
    const float4* wp = (const float4*)(w_ij + (size_t)eid * NF_C + off);

    // streaming (evict-first) for the one-shot w_ij stream
    float4 w0 = __ldcs(wp);
    float4 w1 = __ldcs(wp + 1);
    uint4  qu = __ldg(qp);
    uint4  ku = __ldg(kp);

    float s = dot8_h(qu, ku, w0, w1);

    // reduce within 8-lane head segment
    s += __shfl_xor_sync(0xffffffffu, s, 1);
    s += __shfl_xor_sync(0xffffffffu, s, 2);
    s += __shfl_xor_sync(0xffffffffu, s, 4);

    float alpha = s * 0.125f * ph;   // 1/sqrt(64) = 0.125

    uint4 vu = __ldg(vp);
    const __half2* v2 = (const __half2*)&vu;
    float2 vf0 = __half22float2(v2[0]);
    float2 vf1 = __half22float2(v2[1]);
    float2 vf2 = __half22float2(v2[2]);
    float2 vf3 = __half22float2(v2[3]);

    float* yp = y + (size_t)i * NF_C + off;

    asm volatile("red.global.add.v4.f32 [%0], {%1, %2, %3, %4};"
                 :: "l"(yp), "f"(alpha * vf0.x), "f"(alpha * vf0.y),
                    "f"(alpha * vf1.x), "f"(alpha * vf1.y) : "memory");
    asm volatile("red.global.add.v4.f32 [%0], {%1, %2, %3, %4};"
                 :: "l"(yp + 4), "f"(alpha * vf2.x), "f"(alpha * vf2.y),
                    "f"(alpha * vf3.x), "f"(alpha * vf3.y) : "memory");
}

// ---------------------------------------------------------------------------
// launch
// ---------------------------------------------------------------------------
extern "C" void kernel_launch(void* const* d_in, const int* in_sizes, int n_in,
                              void* d_out, int out_size) {
    const float* x     = (const float*)d_in[0];
    const float* w_ij  = (const float*)d_in[1];
    const int*   idx_i = (const int*)d_in[2];
    const int*   idx_j = (const int*)d_in[3];
    const float* phi   = (const float*)d_in[4];
    const float* Wq    = (const float*)d_in[5];
    const float* Wk    = (const float*)d_in[6];
    const float* Wv    = (const float*)d_in[7];
    float* y = (float*)d_out;

    cudaMemsetAsync(y, 0, (size_t)N_NODES_C * NF_C * sizeof(float), 0);

    static const size_t smem_bytes = SMEM_FLOATS * sizeof(float);
    cudaFuncSetAttribute(proj_kernel, cudaFuncAttributeMaxDynamicSharedMemorySize,
                         (int)smem_bytes);

    dim3 pgrid((N_NODES_C + TILE_N - 1) / TILE_N, NHEADS_C);
    proj_kernel<<<pgrid, PROJ_THREADS, smem_bytes>>>(x, Wq, Wk, Wv);

    int warps_per_block = 256 / 32;
    int nblocks = (N_PAIRS_C + warps_per_block - 1) / warps_per_block;
    edge_kernel<<<nblocks, 256>>>(w_ij, idx_i, idx_j, phi, y);
}

// round 3
// speedup vs baseline: 1.5111x; 1.1869x over previous
#include <cuda_runtime.h>
#include <cuda_fp16.h>
#include <cstdint>

#define N_NODES_C 50000
#define N_PAIRS_C 800000
#define NHEADS_C 4
#define HEAD_DIM_C 64
#define NF_C 256   // NHEADS*HEAD_DIM

// scratch (allocation-free rule: __device__ globals)
__device__ __half g_q[N_NODES_C * NF_C];
__device__ __half g_k[N_NODES_C * NF_C];
__device__ __half g_v[N_NODES_C * NF_C];

__device__ int g_cnt[N_NODES_C + 1];     // histogram
__device__ int g_off[N_NODES_C + 1];     // CSR offsets (exclusive scan)
__device__ int g_cur[N_NODES_C + 1];     // scatter cursors
__device__ int g_sorted[N_PAIRS_C];      // edge ids grouped by idx_i

// ---------------------------------------------------------------------------
// packed f32x2 helpers (proj kernel)
// ---------------------------------------------------------------------------
__device__ __forceinline__ void fma2(unsigned long long& d, unsigned long long a,
                                     unsigned long long b) {
    asm("fma.rn.f32x2 %0, %1, %2, %0;" : "+l"(d) : "l"(a), "l"(b));
}
__device__ __forceinline__ unsigned long long bcast2(float w) {
    unsigned long long r;
    asm("mov.b64 %0, {%1, %1};" : "=l"(r) : "f"(w));
    return r;
}
__device__ __forceinline__ void unpack2(unsigned long long u, float& lo, float& hi) {
    asm("mov.b64 {%0, %1}, %2;" : "=f"(lo), "=f"(hi) : "l"(u));
}

union F4U2 { float4 f4; unsigned long long u2[2]; };

// ---------------------------------------------------------------------------
// Kernel 1: per-head projections q,k,v (fp32 compute, fp16 store). unchanged.
// ---------------------------------------------------------------------------
#define TILE_N 64
#define PROJ_THREADS 256
#define SW_PITCH 65
#define SX_PITCH 68
#define SW_MAT (64 * SW_PITCH)
#define SMEM_FLOATS (3 * SW_MAT + 64 * SX_PITCH)

__global__ void __launch_bounds__(PROJ_THREADS)
proj_kernel(const float* __restrict__ x,
            const float* __restrict__ Wq,
            const float* __restrict__ Wk,
            const float* __restrict__ Wv) {
    extern __shared__ float sm[];
    float* sW = sm;
    float* sX = sm + 3 * SW_MAT;

    const int h   = blockIdx.y;
    const int n0  = blockIdx.x * TILE_N;
    const int tid = threadIdx.x;

    for (int idx = tid; idx < 3 * 64 * 64; idx += PROJ_THREADS) {
        int m = idx >> 12;
        int r = idx & 4095;
        int e = r >> 6, d = r & 63;
        const float* W = (m == 0) ? Wq : ((m == 1) ? Wk : Wv);
        sW[m * SW_MAT + e * SW_PITCH + d] = W[h * 4096 + e * 64 + d];
    }
    for (int idx = tid; idx < TILE_N * 64; idx += PROJ_THREADS) {
        int nl = idx >> 6, d = idx & 63;
        int n = n0 + nl;
        float v = (n < N_NODES_C) ? x[(size_t)n * NF_C + h * HEAD_DIM_C + d] : 0.0f;
        sX[d * SX_PITCH + nl] = v;
    }
    __syncthreads();

    const int e = tid & 63;
    const int g = tid >> 6;

    const float* wqr = sW + 0 * SW_MAT + e * SW_PITCH;
    const float* wkr = sW + 1 * SW_MAT + e * SW_PITCH;
    const float* wvr = sW + 2 * SW_MAT + e * SW_PITCH;

    unsigned long long aq[8], ak[8], av[8];
#pragma unroll
    for (int p = 0; p < 8; p++) { aq[p] = 0ULL; ak[p] = 0ULL; av[p] = 0ULL; }

#pragma unroll 4
    for (int kk = 0; kk < 64; kk++) {
        unsigned long long bq = bcast2(wqr[kk]);
        unsigned long long bk = bcast2(wkr[kk]);
        unsigned long long bv = bcast2(wvr[kk]);
        const float4* xp = (const float4*)(sX + kk * SX_PITCH + g * 16);
        F4U2 x0, x1, x2, x3;
        x0.f4 = xp[0]; x1.f4 = xp[1]; x2.f4 = xp[2]; x3.f4 = xp[3];
        unsigned long long xu[8] = {x0.u2[0], x0.u2[1], x1.u2[0], x1.u2[1],
                                    x2.u2[0], x2.u2[1], x3.u2[0], x3.u2[1]};
#pragma unroll
        for (int p = 0; p < 8; p++) {
            fma2(aq[p], xu[p], bq);
            fma2(ak[p], xu[p], bk);
            fma2(av[p], xu[p], bv);
        }
    }

#pragma unroll
    for (int p = 0; p < 8; p++) {
        float qlo, qhi, klo, khi, vlo, vhi;
        unpack2(aq[p], qlo, qhi);
        unpack2(ak[p], klo, khi);
        unpack2(av[p], vlo, vhi);
        int nl = g * 16 + 2 * p;
        int n  = n0 + nl;
        if (n < N_NODES_C) {
            size_t o = (size_t)n * NF_C + h * HEAD_DIM_C + e;
            g_q[o] = __float2half_rn(qlo);
            g_k[o] = __float2half_rn(klo);
            g_v[o] = __float2half_rn(vlo);
        }
        if (n + 1 < N_NODES_C) {
            size_t o = (size_t)(n + 1) * NF_C + h * HEAD_DIM_C + e;
            g_q[o] = __float2half_rn(qhi);
            g_k[o] = __float2half_rn(khi);
            g_v[o] = __float2half_rn(vhi);
        }
    }
}

// ---------------------------------------------------------------------------
// Sort pipeline: build CSR of edges grouped by idx_i
// ---------------------------------------------------------------------------
__global__ void zero_cnt_kernel() {
    int t = blockIdx.x * blockDim.x + threadIdx.x;
    if (t <= N_NODES_C) g_cnt[t] = 0;
}

__global__ void hist_kernel(const int* __restrict__ idx_i) {
    int e = blockIdx.x * blockDim.x + threadIdx.x;
    if (e < N_PAIRS_C) atomicAdd(&g_cnt[idx_i[e]], 1);
}

// single-block exclusive scan over g_cnt[0..N_NODES_C) -> g_off, g_cur
#define SCAN_THREADS 1024
__global__ void __launch_bounds__(SCAN_THREADS)
scan_kernel() {
    __shared__ int swarp[32];
    __shared__ int scarry;
    const int tid  = threadIdx.x;
    const int lane = tid & 31;
    const int wid  = tid >> 5;
    if (tid == 0) scarry = 0;
    __syncthreads();

    for (int base = 0; base < N_NODES_C; base += SCAN_THREADS) {
        int i = base + tid;
        int v = (i < N_NODES_C) ? g_cnt[i] : 0;
        int orig = v;
        // inclusive warp scan
#pragma unroll
        for (int o = 1; o < 32; o <<= 1) {
            int n = __shfl_up_sync(0xffffffffu, v, o);
            if (lane >= o) v += n;
        }
        if (lane == 31) swarp[wid] = v;
        __syncthreads();
        if (wid == 0) {
            int x = swarp[lane];
#pragma unroll
            for (int o = 1; o < 32; o <<= 1) {
                int n = __shfl_up_sync(0xffffffffu, x, o);
                if (lane >= o) x += n;
            }
            swarp[lane] = x;
        }
        __syncthreads();
        int incl = v + (wid > 0 ? swarp[wid - 1] : 0);
        int excl = scarry + incl - orig;
        if (i < N_NODES_C) { g_off[i] = excl; g_cur[i] = excl; }
        int chunk_total = swarp[31];
        __syncthreads();
        if (tid == 0) scarry += chunk_total;
        __syncthreads();
    }
    if (tid == 0) g_off[N_NODES_C] = scarry;   // = N_PAIRS_C
}

__global__ void scatter_kernel(const int* __restrict__ idx_i) {
    int e = blockIdx.x * blockDim.x + threadIdx.x;
    if (e < N_PAIRS_C) {
        int pos = atomicAdd(&g_cur[idx_i[e]], 1);
        g_sorted[pos] = e;
    }
}

// ---------------------------------------------------------------------------
// Grouped edge kernel: one warp per node. Lane owns 8 dims (head = lane/8).
// q[i] loaded once; edges streamed; y[i] accumulated in regs, plain STG.
// ---------------------------------------------------------------------------
__global__ void __launch_bounds__(256)
edge_grouped_kernel(const float* __restrict__ w_ij,
                    const int* __restrict__ idx_j,
                    const float* __restrict__ phi,
                    float* __restrict__ y) {
    int node = (blockIdx.x * blockDim.x + threadIdx.x) >> 5;
    int lane = threadIdx.x & 31;
    if (node >= N_NODES_C) return;

    const int start = g_off[node];
    const int end   = g_off[node + 1];
    const int off   = lane * 8;

    // q[i] once, unpacked to fp32
    uint4 qu = *(const uint4*)(g_q + (size_t)node * NF_C + off);
    const __half2* q2 = (const __half2*)&qu;
    float2 qf0 = __half22float2(q2[0]);
    float2 qf1 = __half22float2(q2[1]);
    float2 qf2 = __half22float2(q2[2]);
    float2 qf3 = __half22float2(q2[3]);

    float a0 = 0.f, a1 = 0.f, a2 = 0.f, a3 = 0.f;
    float a4 = 0.f, a5 = 0.f, a6 = 0.f, a7 = 0.f;

    for (int t = start; t < end; ++t) {
        int   e  = g_sorted[t];
        int   j  = __ldg(&idx_j[e]);
        float ph = __ldg(&phi[e]);

        const float4* wp = (const float4*)(w_ij + (size_t)e * NF_C + off);
        float4 w0 = __ldcs(wp);
        float4 w1 = __ldcs(wp + 1);
        uint4 ku = __ldg((const uint4*)(g_k + (size_t)j * NF_C + off));
        uint4 vu = __ldg((const uint4*)(g_v + (size_t)j * NF_C + off));

        const __half2* k2 = (const __half2*)&ku;
        float2 kf0 = __half22float2(k2[0]);
        float2 kf1 = __half22float2(k2[1]);
        float2 kf2 = __half22float2(k2[2]);
        float2 kf3 = __half22float2(k2[3]);

        float s;
        s  = qf0.x * w0.x * kf0.x;
        s += qf0.y * w0.y * kf0.y;
        s += qf1.x * w0.z * kf1.x;
        s += qf1.y * w0.w * kf1.y;
        s += qf2.x * w1.x * kf2.x;
        s += qf2.y * w1.y * kf2.y;
        s += qf3.x * w1.z * kf3.x;
        s += qf3.y * w1.w * kf3.y;

        // reduce within 8-lane head segment
        s += __shfl_xor_sync(0xffffffffu, s, 1);
        s += __shfl_xor_sync(0xffffffffu, s, 2);
        s += __shfl_xor_sync(0xffffffffu, s, 4);

        float alpha = s * 0.125f * ph;

        const __half2* v2 = (const __half2*)&vu;
        float2 vf0 = __half22float2(v2[0]);
        float2 vf1 = __half22float2(v2[1]);
        float2 vf2 = __half22float2(v2[2]);
        float2 vf3 = __half22float2(v2[3]);

        a0 = fmaf(alpha, vf0.x, a0);
        a1 = fmaf(alpha, vf0.y, a1);
        a2 = fmaf(alpha, vf1.x, a2);
        a3 = fmaf(alpha, vf1.y, a3);
        a4 = fmaf(alpha, vf2.x, a4);
        a5 = fmaf(alpha, vf2.y, a5);
        a6 = fmaf(alpha, vf3.x, a6);
        a7 = fmaf(alpha, vf3.y, a7);
    }

    float4* yp = (float4*)(y + (size_t)node * NF_C + off);
    yp[0] = make_float4(a0, a1, a2, a3);
    yp[1] = make_float4(a4, a5, a6, a7);
}

// ---------------------------------------------------------------------------
// launch
// ---------------------------------------------------------------------------
extern "C" void kernel_launch(void* const* d_in, const int* in_sizes, int n_in,
                              void* d_out, int out_size) {
    const float* x     = (const float*)d_in[0];
    const float* w_ij  = (const float*)d_in[1];
    const int*   idx_i = (const int*)d_in[2];
    const int*   idx_j = (const int*)d_in[3];
    const float* phi   = (const float*)d_in[4];
    const float* Wq    = (const float*)d_in[5];
    const float* Wk    = (const float*)d_in[6];
    const float* Wv    = (const float*)d_in[7];
    float* y = (float*)d_out;

    static const size_t smem_bytes = SMEM_FLOATS * sizeof(float);
    cudaFuncSetAttribute(proj_kernel, cudaFuncAttributeMaxDynamicSharedMemorySize,
                         (int)smem_bytes);

    // CSR build
    zero_cnt_kernel<<<(N_NODES_C + 256) / 256, 256>>>();
    hist_kernel<<<(N_PAIRS_C + 255) / 256, 256>>>(idx_i);
    scan_kernel<<<1, SCAN_THREADS>>>();
    scatter_kernel<<<(N_PAIRS_C + 255) / 256, 256>>>(idx_i);

    // projections
    dim3 pgrid((N_NODES_C + TILE_N - 1) / TILE_N, NHEADS_C);
    proj_kernel<<<pgrid, PROJ_THREADS, smem_bytes>>>(x, Wq, Wk, Wv);

    // grouped edge accumulation: one warp per node
    int warps_per_block = 256 / 32;
    int nblocks = (N_NODES_C + warps_per_block - 1) / warps_per_block;
    edge_grouped_kernel<<<nblocks, 256>>>(w_ij, idx_j, phi, y);
}

// round 4
// speedup vs baseline: 1.5804x; 1.0458x over previous
#include <cuda_runtime.h>
#include <cuda_fp16.h>
#include <cstdint>

#define N_NODES_C 50000
#define N_PAIRS_C 800000
#define NHEADS_C 4
#define HEAD_DIM_C 64
#define NF_C 256   // NHEADS*HEAD_DIM
#define CAP 96     // max in-degree per bucket (mean 16, Poisson)
#define OVF_CAP 4096

// scratch (allocation-free rule: __device__ globals)
__device__ __half g_q[N_NODES_C * NF_C];
__device__ __half g_k[N_NODES_C * NF_C];
__device__ __half g_v[N_NODES_C * NF_C];

__device__ int   g_cnt[N_NODES_C];
__device__ int2  g_bkt[(size_t)N_NODES_C * CAP];    // {edge id, idx_j}
__device__ float g_bphi[(size_t)N_NODES_C * CAP];
__device__ int   g_ovf_cnt;
__device__ int   g_ovf[OVF_CAP];

// ---------------------------------------------------------------------------
// packed f32x2 helpers (proj kernel)
// ---------------------------------------------------------------------------
__device__ __forceinline__ void fma2(unsigned long long& d, unsigned long long a,
                                     unsigned long long b) {
    asm("fma.rn.f32x2 %0, %1, %2, %0;" : "+l"(d) : "l"(a), "l"(b));
}
__device__ __forceinline__ unsigned long long bcast2(float w) {
    unsigned long long r;
    asm("mov.b64 %0, {%1, %1};" : "=l"(r) : "f"(w));
    return r;
}
__device__ __forceinline__ void unpack2(unsigned long long u, float& lo, float& hi) {
    asm("mov.b64 {%0, %1}, %2;" : "=f"(lo), "=f"(hi) : "l"(u));
}

union F4U2 { float4 f4; unsigned long long u2[2]; };

// ---------------------------------------------------------------------------
// Kernel 1: per-head projections q,k,v (fp32 compute, fp16 store).
// ---------------------------------------------------------------------------
#define TILE_N 64
#define PROJ_THREADS 256
#define SW_PITCH 65
#define SX_PITCH 68
#define SW_MAT (64 * SW_PITCH)
#define SMEM_FLOATS (3 * SW_MAT + 64 * SX_PITCH)

__global__ void __launch_bounds__(PROJ_THREADS)
proj_kernel(const float* __restrict__ x,
            const float* __restrict__ Wq,
            const float* __restrict__ Wk,
            const float* __restrict__ Wv) {
    extern __shared__ float sm[];
    float* sW = sm;
    float* sX = sm + 3 * SW_MAT;

    const int h   = blockIdx.y;
    const int n0  = blockIdx.x * TILE_N;
    const int tid = threadIdx.x;

    for (int idx = tid; idx < 3 * 64 * 64; idx += PROJ_THREADS) {
        int m = idx >> 12;
        int r = idx & 4095;
        int e = r >> 6, d = r & 63;
        const float* W = (m == 0) ? Wq : ((m == 1) ? Wk : Wv);
        sW[m * SW_MAT + e * SW_PITCH + d] = W[h * 4096 + e * 64 + d];
    }
    for (int idx = tid; idx < TILE_N * 64; idx += PROJ_THREADS) {
        int nl = idx >> 6, d = idx & 63;
        int n = n0 + nl;
        float v = (n < N_NODES_C) ? x[(size_t)n * NF_C + h * HEAD_DIM_C + d] : 0.0f;
        sX[d * SX_PITCH + nl] = v;
    }
    __syncthreads();

    const int e = tid & 63;
    const int g = tid >> 6;

    const float* wqr = sW + 0 * SW_MAT + e * SW_PITCH;
    const float* wkr = sW + 1 * SW_MAT + e * SW_PITCH;
    const float* wvr = sW + 2 * SW_MAT + e * SW_PITCH;

    unsigned long long aq[8], ak[8], av[8];
#pragma unroll
    for (int p = 0; p < 8; p++) { aq[p] = 0ULL; ak[p] = 0ULL; av[p] = 0ULL; }

#pragma unroll 4
    for (int kk = 0; kk < 64; kk++) {
        unsigned long long bq = bcast2(wqr[kk]);
        unsigned long long bk = bcast2(wkr[kk]);
        unsigned long long bv = bcast2(wvr[kk]);
        const float4* xp = (const float4*)(sX + kk * SX_PITCH + g * 16);
        F4U2 x0, x1, x2, x3;
        x0.f4 = xp[0]; x1.f4 = xp[1]; x2.f4 = xp[2]; x3.f4 = xp[3];
        unsigned long long xu[8] = {x0.u2[0], x0.u2[1], x1.u2[0], x1.u2[1],
                                    x2.u2[0], x2.u2[1], x3.u2[0], x3.u2[1]};
#pragma unroll
        for (int p = 0; p < 8; p++) {
            fma2(aq[p], xu[p], bq);
            fma2(ak[p], xu[p], bk);
            fma2(av[p], xu[p], bv);
        }
    }

#pragma unroll
    for (int p = 0; p < 8; p++) {
        float qlo, qhi, klo, khi, vlo, vhi;
        unpack2(aq[p], qlo, qhi);
        unpack2(ak[p], klo, khi);
        unpack2(av[p], vlo, vhi);
        int nl = g * 16 + 2 * p;
        int n  = n0 + nl;
        if (n < N_NODES_C) {
            size_t o = (size_t)n * NF_C + h * HEAD_DIM_C + e;
            g_q[o] = __float2half_rn(qlo);
            g_k[o] = __float2half_rn(klo);
            g_v[o] = __float2half_rn(vlo);
        }
        if (n + 1 < N_NODES_C) {
            size_t o = (size_t)(n + 1) * NF_C + h * HEAD_DIM_C + e;
            g_q[o] = __float2half_rn(qhi);
            g_k[o] = __float2half_rn(khi);
            g_v[o] = __float2half_rn(vhi);
        }
    }
}

// ---------------------------------------------------------------------------
// Bucket build: zero counters, then direct scatter of {e, j, phi}
// ---------------------------------------------------------------------------
__global__ void zero_cnt_kernel() {
    int t = blockIdx.x * blockDim.x + threadIdx.x;
    if (t < N_NODES_C) g_cnt[t] = 0;
    if (t == 0) g_ovf_cnt = 0;
}

__global__ void bucket_kernel(const int* __restrict__ idx_i,
                              const int* __restrict__ idx_j,
                              const float* __restrict__ phi) {
    int e = blockIdx.x * blockDim.x + threadIdx.x;
    if (e >= N_PAIRS_C) return;
    int i = idx_i[e];
    int pos = atomicAdd(&g_cnt[i], 1);
    if (pos < CAP) {
        size_t o = (size_t)i * CAP + pos;
        g_bkt[o]  = make_int2(e, idx_j[e]);
        g_bphi[o] = phi[e];
    } else {
        int p = atomicAdd(&g_ovf_cnt, 1);
        if (p < OVF_CAP) g_ovf[p] = e;
    }
}

// ---------------------------------------------------------------------------
// dot helper: 8 dims fp16 q/k with fp32 w
// ---------------------------------------------------------------------------
__device__ __forceinline__ float dot8_h(uint4 qu, uint4 ku, float4 w0, float4 w1) {
    const __half2* q2 = (const __half2*)&qu;
    const __half2* k2 = (const __half2*)&ku;
    float2 qf0 = __half22float2(q2[0]);
    float2 qf1 = __half22float2(q2[1]);
    float2 qf2 = __half22float2(q2[2]);
    float2 qf3 = __half22float2(q2[3]);
    float2 kf0 = __half22float2(k2[0]);
    float2 kf1 = __half22float2(k2[1]);
    float2 kf2 = __half22float2(k2[2]);
    float2 kf3 = __half22float2(k2[3]);
    float s;
    s  = qf0.x * w0.x * kf0.x;
    s += qf0.y * w0.y * kf0.y;
    s += qf1.x * w0.z * kf1.x;
    s += qf1.y * w0.w * kf1.y;
    s += qf2.x * w1.x * kf2.x;
    s += qf2.y * w1.y * kf2.y;
    s += qf3.x * w1.z * kf3.x;
    s += qf3.y * w1.w * kf3.y;
    return s;
}

__device__ __forceinline__ float dot8_qf(const float2* qf, uint4 ku,
                                         float4 w0, float4 w1) {
    const __half2* k2 = (const __half2*)&ku;
    float2 kf0 = __half22float2(k2[0]);
    float2 kf1 = __half22float2(k2[1]);
    float2 kf2 = __half22float2(k2[2]);
    float2 kf3 = __half22float2(k2[3]);
    float s;
    s  = qf[0].x * w0.x * kf0.x;
    s += qf[0].y * w0.y * kf0.y;
    s += qf[1].x * w0.z * kf1.x;
    s += qf[1].y * w0.w * kf1.y;
    s += qf[2].x * w1.x * kf2.x;
    s += qf[2].y * w1.y * kf2.y;
    s += qf[3].x * w1.z * kf3.x;
    s += qf[3].y * w1.w * kf3.y;
    return s;
}

// ---------------------------------------------------------------------------
// Grouped edge kernel: one warp per node, 2-edge unrolled for MLP.
// ---------------------------------------------------------------------------
__global__ void __launch_bounds__(256)
edge_grouped_kernel(const float* __restrict__ w_ij,
                    float* __restrict__ y) {
    int node = (blockIdx.x * blockDim.x + threadIdx.x) >> 5;
    int lane = threadIdx.x & 31;
    if (node >= N_NODES_C) return;

    int deg = g_cnt[node];
    if (deg > CAP) deg = CAP;
    const size_t base = (size_t)node * CAP;
    const int off = lane * 8;

    // q[i] once, unpacked to fp32
    uint4 qu = *(const uint4*)(g_q + (size_t)node * NF_C + off);
    const __half2* q2 = (const __half2*)&qu;
    float2 qf[4];
    qf[0] = __half22float2(q2[0]);
    qf[1] = __half22float2(q2[1]);
    qf[2] = __half22float2(q2[2]);
    qf[3] = __half22float2(q2[3]);

    float a0 = 0.f, a1 = 0.f, a2 = 0.f, a3 = 0.f;
    float a4 = 0.f, a5 = 0.f, a6 = 0.f, a7 = 0.f;

    int t = 0;
    for (; t + 2 <= deg; t += 2) {
        // --- issue all loads for both edges first (MLP) ---
        int2  m0 = g_bkt[base + t];
        int2  m1 = g_bkt[base + t + 1];
        float p0 = g_bphi[base + t];
        float p1 = g_bphi[base + t + 1];

        const float4* wp0 = (const float4*)(w_ij + (size_t)m0.x * NF_C + off);
        const float4* wp1 = (const float4*)(w_ij + (size_t)m1.x * NF_C + off);
        float4 w00 = __ldcs(wp0);
        float4 w01 = __ldcs(wp0 + 1);
        float4 w10 = __ldcs(wp1);
        float4 w11 = __ldcs(wp1 + 1);

        uint4 ku0 = __ldg((const uint4*)(g_k + (size_t)m0.y * NF_C + off));
        uint4 vu0 = __ldg((const uint4*)(g_v + (size_t)m0.y * NF_C + off));
        uint4 ku1 = __ldg((const uint4*)(g_k + (size_t)m1.y * NF_C + off));
        uint4 vu1 = __ldg((const uint4*)(g_v + (size_t)m1.y * NF_C + off));

        float s0 = dot8_qf(qf, ku0, w00, w01);
        float s1 = dot8_qf(qf, ku1, w10, w11);

        s0 += __shfl_xor_sync(0xffffffffu, s0, 1);
        s1 += __shfl_xor_sync(0xffffffffu, s1, 1);
        s0 += __shfl_xor_sync(0xffffffffu, s0, 2);
        s1 += __shfl_xor_sync(0xffffffffu, s1, 2);
        s0 += __shfl_xor_sync(0xffffffffu, s0, 4);
        s1 += __shfl_xor_sync(0xffffffffu, s1, 4);

        float al0 = s0 * 0.125f * p0;
        float al1 = s1 * 0.125f * p1;

        const __half2* v20 = (const __half2*)&vu0;
        const __half2* v21 = (const __half2*)&vu1;
        float2 f;
        f = __half22float2(v20[0]); a0 = fmaf(al0, f.x, a0); a1 = fmaf(al0, f.y, a1);
        f = __half22float2(v20[1]); a2 = fmaf(al0, f.x, a2); a3 = fmaf(al0, f.y, a3);
        f = __half22float2(v20[2]); a4 = fmaf(al0, f.x, a4); a5 = fmaf(al0, f.y, a5);
        f = __half22float2(v20[3]); a6 = fmaf(al0, f.x, a6); a7 = fmaf(al0, f.y, a7);
        f = __half22float2(v21[0]); a0 = fmaf(al1, f.x, a0); a1 = fmaf(al1, f.y, a1);
        f = __half22float2(v21[1]); a2 = fmaf(al1, f.x, a2); a3 = fmaf(al1, f.y, a3);
        f = __half22float2(v21[2]); a4 = fmaf(al1, f.x, a4); a5 = fmaf(al1, f.y, a5);
        f = __half22float2(v21[3]); a6 = fmaf(al1, f.x, a6); a7 = fmaf(al1, f.y, a7);
    }
    if (t < deg) {
        int2  m0 = g_bkt[base + t];
        float p0 = g_bphi[base + t];
        const float4* wp0 = (const float4*)(w_ij + (size_t)m0.x * NF_C + off);
        float4 w00 = __ldcs(wp0);
        float4 w01 = __ldcs(wp0 + 1);
        uint4 ku0 = __ldg((const uint4*)(g_k + (size_t)m0.y * NF_C + off));
        uint4 vu0 = __ldg((const uint4*)(g_v + (size_t)m0.y * NF_C + off));

        float s0 = dot8_qf(qf, ku0, w00, w01);
        s0 += __shfl_xor_sync(0xffffffffu, s0, 1);
        s0 += __shfl_xor_sync(0xffffffffu, s0, 2);
        s0 += __shfl_xor_sync(0xffffffffu, s0, 4);
        float al0 = s0 * 0.125f * p0;

        const __half2* v20 = (const __half2*)&vu0;
        float2 f;
        f = __half22float2(v20[0]); a0 = fmaf(al0, f.x, a0); a1 = fmaf(al0, f.y, a1);
        f = __half22float2(v20[1]); a2 = fmaf(al0, f.x, a2); a3 = fmaf(al0, f.y, a3);
        f = __half22float2(v20[2]); a4 = fmaf(al0, f.x, a4); a5 = fmaf(al0, f.y, a5);
        f = __half22float2(v20[3]); a6 = fmaf(al0, f.x, a6); a7 = fmaf(al0, f.y, a7);
    }

    float4* yp = (float4*)(y + (size_t)node * NF_C + off);
    yp[0] = make_float4(a0, a1, a2, a3);
    yp[1] = make_float4(a4, a5, a6, a7);
}

// ---------------------------------------------------------------------------
// Overflow fallback (virtually never has work): atomic adds on top of y.
// ---------------------------------------------------------------------------
__global__ void overflow_kernel(const float* __restrict__ w_ij,
                                const int* __restrict__ idx_i,
                                const int* __restrict__ idx_j,
                                const float* __restrict__ phi,
                                float* __restrict__ y) {
    int n = g_ovf_cnt;
    if (n > OVF_CAP) n = OVF_CAP;
    int lane = threadIdx.x & 31;
    for (int t = (int)(threadIdx.x >> 5); t < n; t += (int)(blockDim.x >> 5)) {
        int e = g_ovf[t];
        int i = idx_i[e];
        int j = idx_j[e];
        float ph = phi[e];
        int off = lane * 8;

        uint4 qu = *(const uint4*)(g_q + (size_t)i * NF_C + off);
        uint4 ku = *(const uint4*)(g_k + (size_t)j * NF_C + off);
        uint4 vu = *(const uint4*)(g_v + (size_t)j * NF_C + off);
        const float4* wp = (const float4*)(w_ij + (size_t)e * NF_C + off);
        float4 w0 = wp[0], w1 = wp[1];

        float s = dot8_h(qu, ku, w0, w1);
        s += __shfl_xor_sync(0xffffffffu, s, 1);
        s += __shfl_xor_sync(0xffffffffu, s, 2);
        s += __shfl_xor_sync(0xffffffffu, s, 4);
        float alpha = s * 0.125f * ph;

        const __half2* v2 = (const __half2*)&vu;
        float2 f0 = __half22float2(v2[0]);
        float2 f1 = __half22float2(v2[1]);
        float2 f2 = __half22float2(v2[2]);
        float2 f3 = __half22float2(v2[3]);
        float* yp = y + (size_t)i * NF_C + off;
        atomicAdd(yp + 0, alpha * f0.x);
        atomicAdd(yp + 1, alpha * f0.y);
        atomicAdd(yp + 2, alpha * f1.x);
        atomicAdd(yp + 3, alpha * f1.y);
        atomicAdd(yp + 4, alpha * f2.x);
        atomicAdd(yp + 5, alpha * f2.y);
        atomicAdd(yp + 6, alpha * f3.x);
        atomicAdd(yp + 7, alpha * f3.y);
    }
}

// ---------------------------------------------------------------------------
// launch
// ---------------------------------------------------------------------------
extern "C" void kernel_launch(void* const* d_in, const int* in_sizes, int n_in,
                              void* d_out, int out_size) {
    const float* x     = (const float*)d_in[0];
    const float* w_ij  = (const float*)d_in[1];
    const int*   idx_i = (const int*)d_in[2];
    const int*   idx_j = (const int*)d_in[3];
    const float* phi   = (const float*)d_in[4];
    const float* Wq    = (const float*)d_in[5];
    const float* Wk    = (const float*)d_in[6];
    const float* Wv    = (const float*)d_in[7];
    float* y = (float*)d_out;

    static const size_t smem_bytes = SMEM_FLOATS * sizeof(float);
    cudaFuncSetAttribute(proj_kernel, cudaFuncAttributeMaxDynamicSharedMemorySize,
                         (int)smem_bytes);

    // bucket build
    zero_cnt_kernel<<<(N_NODES_C + 255) / 256, 256>>>();
    bucket_kernel<<<(N_PAIRS_C + 255) / 256, 256>>>(idx_i, idx_j, phi);

    // projections
    dim3 pgrid((N_NODES_C + TILE_N - 1) / TILE_N, NHEADS_C);
    proj_kernel<<<pgrid, PROJ_THREADS, smem_bytes>>>(x, Wq, Wk, Wv);

    // grouped edge accumulation: one warp per node
    int warps_per_block = 256 / 32;
    int nblocks = (N_NODES_C + warps_per_block - 1) / warps_per_block;
    edge_grouped_kernel<<<nblocks, 256>>>(w_ij, y);

    // overflow (usually empty)
    overflow_kernel<<<1, 256>>>(w_ij, idx_i, idx_j, phi, y);
}

// round 5
// speedup vs baseline: 1.6288x; 1.0306x over previous
#include <cuda_runtime.h>
#include <cuda_fp16.h>
#include <cstdint>

#define N_NODES_C 50000
#define N_PAIRS_C 800000
#define NHEADS_C 4
#define HEAD_DIM_C 64
#define NF_C 256   // NHEADS*HEAD_DIM
#define CAP 96     // max in-degree per bucket (mean 16, Poisson)
#define OVF_CAP 4096

// scratch (allocation-free rule: __device__ globals)
__device__ __half g_q[N_NODES_C * NF_C];
__device__ __half g_k[N_NODES_C * NF_C];
__device__ __half g_v[N_NODES_C * NF_C];
__device__ float  g_alpha[(size_t)N_PAIRS_C * NHEADS_C];   // 12.8 MB

__device__ int   g_cnt[N_NODES_C];
__device__ int2  g_bkt[(size_t)N_NODES_C * CAP];    // {edge id, idx_j}
__device__ int   g_ovf_cnt;
__device__ int   g_ovf[OVF_CAP];

// ---------------------------------------------------------------------------
// packed f32x2 helpers (proj kernel)
// ---------------------------------------------------------------------------
__device__ __forceinline__ void fma2(unsigned long long& d, unsigned long long a,
                                     unsigned long long b) {
    asm("fma.rn.f32x2 %0, %1, %2, %0;" : "+l"(d) : "l"(a), "l"(b));
}
__device__ __forceinline__ unsigned long long bcast2(float w) {
    unsigned long long r;
    asm("mov.b64 %0, {%1, %1};" : "=l"(r) : "f"(w));
    return r;
}
__device__ __forceinline__ void unpack2(unsigned long long u, float& lo, float& hi) {
    asm("mov.b64 {%0, %1}, %2;" : "=f"(lo), "=f"(hi) : "l"(u));
}

union F4U2 { float4 f4; unsigned long long u2[2]; };

// ---------------------------------------------------------------------------
// Kernel 1: per-head projections q,k,v (fp32 compute, fp16 store).
// ---------------------------------------------------------------------------
#define TILE_N 64
#define PROJ_THREADS 256
#define SW_PITCH 65
#define SX_PITCH 68
#define SW_MAT (64 * SW_PITCH)
#define SMEM_FLOATS (3 * SW_MAT + 64 * SX_PITCH)

__global__ void __launch_bounds__(PROJ_THREADS)
proj_kernel(const float* __restrict__ x,
            const float* __restrict__ Wq,
            const float* __restrict__ Wk,
            const float* __restrict__ Wv) {
    extern __shared__ float sm[];
    float* sW = sm;
    float* sX = sm + 3 * SW_MAT;

    const int h   = blockIdx.y;
    const int n0  = blockIdx.x * TILE_N;
    const int tid = threadIdx.x;

    for (int idx = tid; idx < 3 * 64 * 64; idx += PROJ_THREADS) {
        int m = idx >> 12;
        int r = idx & 4095;
        int e = r >> 6, d = r & 63;
        const float* W = (m == 0) ? Wq : ((m == 1) ? Wk : Wv);
        sW[m * SW_MAT + e * SW_PITCH + d] = W[h * 4096 + e * 64 + d];
    }
    for (int idx = tid; idx < TILE_N * 64; idx += PROJ_THREADS) {
        int nl = idx >> 6, d = idx & 63;
        int n = n0 + nl;
        float v = (n < N_NODES_C) ? x[(size_t)n * NF_C + h * HEAD_DIM_C + d] : 0.0f;
        sX[d * SX_PITCH + nl] = v;
    }
    __syncthreads();

    const int e = tid & 63;
    const int g = tid >> 6;

    const float* wqr = sW + 0 * SW_MAT + e * SW_PITCH;
    const float* wkr = sW + 1 * SW_MAT + e * SW_PITCH;
    const float* wvr = sW + 2 * SW_MAT + e * SW_PITCH;

    unsigned long long aq[8], ak[8], av[8];
#pragma unroll
    for (int p = 0; p < 8; p++) { aq[p] = 0ULL; ak[p] = 0ULL; av[p] = 0ULL; }

#pragma unroll 4
    for (int kk = 0; kk < 64; kk++) {
        unsigned long long bq = bcast2(wqr[kk]);
        unsigned long long bk = bcast2(wkr[kk]);
        unsigned long long bv = bcast2(wvr[kk]);
        const float4* xp = (const float4*)(sX + kk * SX_PITCH + g * 16);
        F4U2 x0, x1, x2, x3;
        x0.f4 = xp[0]; x1.f4 = xp[1]; x2.f4 = xp[2]; x3.f4 = xp[3];
        unsigned long long xu[8] = {x0.u2[0], x0.u2[1], x1.u2[0], x1.u2[1],
                                    x2.u2[0], x2.u2[1], x3.u2[0], x3.u2[1]};
#pragma unroll
        for (int p = 0; p < 8; p++) {
            fma2(aq[p], xu[p], bq);
            fma2(ak[p], xu[p], bk);
            fma2(av[p], xu[p], bv);
        }
    }

#pragma unroll
    for (int p = 0; p < 8; p++) {
        float qlo, qhi, klo, khi, vlo, vhi;
        unpack2(aq[p], qlo, qhi);
        unpack2(ak[p], klo, khi);
        unpack2(av[p], vlo, vhi);
        int nl = g * 16 + 2 * p;
        int n  = n0 + nl;
        if (n < N_NODES_C) {
            size_t o = (size_t)n * NF_C + h * HEAD_DIM_C + e;
            g_q[o] = __float2half_rn(qlo);
            g_k[o] = __float2half_rn(klo);
            g_v[o] = __float2half_rn(vlo);
        }
        if (n + 1 < N_NODES_C) {
            size_t o = (size_t)(n + 1) * NF_C + h * HEAD_DIM_C + e;
            g_q[o] = __float2half_rn(qhi);
            g_k[o] = __float2half_rn(khi);
            g_v[o] = __float2half_rn(vhi);
        }
    }
}

// ---------------------------------------------------------------------------
// Bucket build: zero counters, then direct scatter of {e, j}
// ---------------------------------------------------------------------------
__global__ void zero_cnt_kernel() {
    int t = blockIdx.x * blockDim.x + threadIdx.x;
    if (t < N_NODES_C) g_cnt[t] = 0;
    if (t == 0) g_ovf_cnt = 0;
}

__global__ void bucket_kernel(const int* __restrict__ idx_i,
                              const int* __restrict__ idx_j) {
    int e = blockIdx.x * blockDim.x + threadIdx.x;
    if (e >= N_PAIRS_C) return;
    int i = idx_i[e];
    int pos = atomicAdd(&g_cnt[i], 1);
    if (pos < CAP) {
        g_bkt[(size_t)i * CAP + pos] = make_int2(e, idx_j[e]);
    } else {
        int p = atomicAdd(&g_ovf_cnt, 1);
        if (p < OVF_CAP) g_ovf[p] = e;
    }
}

// ---------------------------------------------------------------------------
// dot helper
// ---------------------------------------------------------------------------
__device__ __forceinline__ float dot8_h(uint4 qu, uint4 ku, float4 w0, float4 w1) {
    const __half2* q2 = (const __half2*)&qu;
    const __half2* k2 = (const __half2*)&ku;
    float2 qf0 = __half22float2(q2[0]);
    float2 qf1 = __half22float2(q2[1]);
    float2 qf2 = __half22float2(q2[2]);
    float2 qf3 = __half22float2(q2[3]);
    float2 kf0 = __half22float2(k2[0]);
    float2 kf1 = __half22float2(k2[1]);
    float2 kf2 = __half22float2(k2[2]);
    float2 kf3 = __half22float2(k2[3]);
    float s;
    s  = qf0.x * w0.x * kf0.x;
    s += qf0.y * w0.y * kf0.y;
    s += qf1.x * w0.z * kf1.x;
    s += qf1.y * w0.w * kf1.y;
    s += qf2.x * w1.x * kf2.x;
    s += qf2.y * w1.y * kf2.y;
    s += qf3.x * w1.z * kf3.x;
    s += qf3.y * w1.w * kf3.y;
    return s;
}

// ---------------------------------------------------------------------------
// Kernel A: alpha stream.  One warp per 2 edges; eid from thread id (no
// indirection).  Coalesced w_ij stream, q/k gathers, writes alpha[e][h].
// ---------------------------------------------------------------------------
__global__ void __launch_bounds__(256)
alpha_kernel(const float* __restrict__ w_ij,
             const int* __restrict__ idx_i,
             const int* __restrict__ idx_j,
             const float* __restrict__ phi) {
    int warp = (blockIdx.x * blockDim.x + threadIdx.x) >> 5;
    int lane = threadIdx.x & 31;
    int e0 = warp * 2;
    if (e0 >= N_PAIRS_C) return;
    int e1 = e0 + 1;          // N_PAIRS even, always valid
    int off = lane * 8;

    int   i0 = __ldg(&idx_i[e0]), i1 = __ldg(&idx_i[e1]);
    int   j0 = __ldg(&idx_j[e0]), j1 = __ldg(&idx_j[e1]);
    float p0 = __ldg(&phi[e0]),   p1 = __ldg(&phi[e1]);

    const float4* wp0 = (const float4*)(w_ij + (size_t)e0 * NF_C + off);
    const float4* wp1 = (const float4*)(w_ij + (size_t)e1 * NF_C + off);
    float4 w00 = __ldcs(wp0);
    float4 w01 = __ldcs(wp0 + 1);
    float4 w10 = __ldcs(wp1);
    float4 w11 = __ldcs(wp1 + 1);

    uint4 qu0 = __ldg((const uint4*)(g_q + (size_t)i0 * NF_C + off));
    uint4 ku0 = __ldg((const uint4*)(g_k + (size_t)j0 * NF_C + off));
    uint4 qu1 = __ldg((const uint4*)(g_q + (size_t)i1 * NF_C + off));
    uint4 ku1 = __ldg((const uint4*)(g_k + (size_t)j1 * NF_C + off));

    float s0 = dot8_h(qu0, ku0, w00, w01);
    float s1 = dot8_h(qu1, ku1, w10, w11);

    s0 += __shfl_xor_sync(0xffffffffu, s0, 1);
    s1 += __shfl_xor_sync(0xffffffffu, s1, 1);
    s0 += __shfl_xor_sync(0xffffffffu, s0, 2);
    s1 += __shfl_xor_sync(0xffffffffu, s1, 2);
    s0 += __shfl_xor_sync(0xffffffffu, s0, 4);
    s1 += __shfl_xor_sync(0xffffffffu, s1, 4);

    if ((lane & 7) == 0) {
        int h = lane >> 3;
        g_alpha[(size_t)e0 * NHEADS_C + h] = s0 * 0.125f * p0;
        g_alpha[(size_t)e1 * NHEADS_C + h] = s1 * 0.125f * p1;
    }
}

// ---------------------------------------------------------------------------
// Kernel B: gather-accumulate.  One warp per node; per edge: {e,j} + alpha
// broadcast + v gather.  Short chain, no shfl, plain STG of y.
// ---------------------------------------------------------------------------
__global__ void __launch_bounds__(256)
accum_kernel(float* __restrict__ y) {
    int node = (blockIdx.x * blockDim.x + threadIdx.x) >> 5;
    int lane = threadIdx.x & 31;
    if (node >= N_NODES_C) return;

    int deg = g_cnt[node];
    if (deg > CAP) deg = CAP;
    const size_t base = (size_t)node * CAP;
    const int off  = lane * 8;
    const int head = lane >> 3;

    float a0 = 0.f, a1 = 0.f, a2 = 0.f, a3 = 0.f;
    float a4 = 0.f, a5 = 0.f, a6 = 0.f, a7 = 0.f;

    int t = 0;
    for (; t + 2 <= deg; t += 2) {
        int2 m0 = g_bkt[base + t];
        int2 m1 = g_bkt[base + t + 1];
        float al0 = __ldg(&g_alpha[(size_t)m0.x * NHEADS_C + head]);
        float al1 = __ldg(&g_alpha[(size_t)m1.x * NHEADS_C + head]);
        uint4 vu0 = __ldg((const uint4*)(g_v + (size_t)m0.y * NF_C + off));
        uint4 vu1 = __ldg((const uint4*)(g_v + (size_t)m1.y * NF_C + off));

        const __half2* v20 = (const __half2*)&vu0;
        const __half2* v21 = (const __half2*)&vu1;
        float2 f;
        f = __half22float2(v20[0]); a0 = fmaf(al0, f.x, a0); a1 = fmaf(al0, f.y, a1);
        f = __half22float2(v20[1]); a2 = fmaf(al0, f.x, a2); a3 = fmaf(al0, f.y, a3);
        f = __half22float2(v20[2]); a4 = fmaf(al0, f.x, a4); a5 = fmaf(al0, f.y, a5);
        f = __half22float2(v20[3]); a6 = fmaf(al0, f.x, a6); a7 = fmaf(al0, f.y, a7);
        f = __half22float2(v21[0]); a0 = fmaf(al1, f.x, a0); a1 = fmaf(al1, f.y, a1);
        f = __half22float2(v21[1]); a2 = fmaf(al1, f.x, a2); a3 = fmaf(al1, f.y, a3);
        f = __half22float2(v21[2]); a4 = fmaf(al1, f.x, a4); a5 = fmaf(al1, f.y, a5);
        f = __half22float2(v21[3]); a6 = fmaf(al1, f.x, a6); a7 = fmaf(al1, f.y, a7);
    }
    if (t < deg) {
        int2 m0 = g_bkt[base + t];
        float al0 = __ldg(&g_alpha[(size_t)m0.x * NHEADS_C + head]);
        uint4 vu0 = __ldg((const uint4*)(g_v + (size_t)m0.y * NF_C + off));
        const __half2* v20 = (const __half2*)&vu0;
        float2 f;
        f = __half22float2(v20[0]); a0 = fmaf(al0, f.x, a0); a1 = fmaf(al0, f.y, a1);
        f = __half22float2(v20[1]); a2 = fmaf(al0, f.x, a2); a3 = fmaf(al0, f.y, a3);
        f = __half22float2(v20[2]); a4 = fmaf(al0, f.x, a4); a5 = fmaf(al0, f.y, a5);
        f = __half22float2(v20[3]); a6 = fmaf(al0, f.x, a6); a7 = fmaf(al0, f.y, a7);
    }

    float4* yp = (float4*)(y + (size_t)node * NF_C + off);
    yp[0] = make_float4(a0, a1, a2, a3);
    yp[1] = make_float4(a4, a5, a6, a7);
}

// ---------------------------------------------------------------------------
// Overflow fallback (virtually never has work): atomic adds on top of y.
// ---------------------------------------------------------------------------
__global__ void overflow_kernel(const int* __restrict__ idx_i,
                                const int* __restrict__ idx_j,
                                float* __restrict__ y) {
    int n = g_ovf_cnt;
    if (n > OVF_CAP) n = OVF_CAP;
    int lane = threadIdx.x & 31;
    for (int t = (int)(threadIdx.x >> 5); t < n; t += (int)(blockDim.x >> 5)) {
        int e = g_ovf[t];
        int i = idx_i[e];
        int j = idx_j[e];
        int off = lane * 8;
        int head = lane >> 3;

        float alpha = g_alpha[(size_t)e * NHEADS_C + head];
        uint4 vu = *(const uint4*)(g_v + (size_t)j * NF_C + off);
        const __half2* v2 = (const __half2*)&vu;
        float2 f0 = __half22float2(v2[0]);
        float2 f1 = __half22float2(v2[1]);
        float2 f2 = __half22float2(v2[2]);
        float2 f3 = __half22float2(v2[3]);
        float* yp = y + (size_t)i * NF_C + off;
        atomicAdd(yp + 0, alpha * f0.x);
        atomicAdd(yp + 1, alpha * f0.y);
        atomicAdd(yp + 2, alpha * f1.x);
        atomicAdd(yp + 3, alpha * f1.y);
        atomicAdd(yp + 4, alpha * f2.x);
        atomicAdd(yp + 5, alpha * f2.y);
        atomicAdd(yp + 6, alpha * f3.x);
        atomicAdd(yp + 7, alpha * f3.y);
    }
}

// ---------------------------------------------------------------------------
// launch
// ---------------------------------------------------------------------------
extern "C" void kernel_launch(void* const* d_in, const int* in_sizes, int n_in,
                              void* d_out, int out_size) {
    const float* x     = (const float*)d_in[0];
    const float* w_ij  = (const float*)d_in[1];
    const int*   idx_i = (const int*)d_in[2];
    const int*   idx_j = (const int*)d_in[3];
    const float* phi   = (const float*)d_in[4];
    const float* Wq    = (const float*)d_in[5];
    const float* Wk    = (const float*)d_in[6];
    const float* Wv    = (const float*)d_in[7];
    float* y = (float*)d_out;

    static const size_t smem_bytes = SMEM_FLOATS * sizeof(float);
    cudaFuncSetAttribute(proj_kernel, cudaFuncAttributeMaxDynamicSharedMemorySize,
                         (int)smem_bytes);

    // bucket build
    zero_cnt_kernel<<<(N_NODES_C + 255) / 256, 256>>>();
    bucket_kernel<<<(N_PAIRS_C + 255) / 256, 256>>>(idx_i, idx_j);

    // projections
    dim3 pgrid((N_NODES_C + TILE_N - 1) / TILE_N, NHEADS_C);
    proj_kernel<<<pgrid, PROJ_THREADS, smem_bytes>>>(x, Wq, Wk, Wv);

    // A: alpha stream  (2 edges per warp -> 8 warps x 2 = 16 edges/block)
    int ablocks = (N_PAIRS_C + 15) / 16;
    alpha_kernel<<<ablocks, 256>>>(w_ij, idx_i, idx_j, phi);

    // B: gather-accumulate, one warp per node
    int nblocks = (N_NODES_C + 7) / 8;
    accum_kernel<<<nblocks, 256>>>(y);

    // overflow (usually empty)
    overflow_kernel<<<1, 256>>>(idx_i, idx_j, y);
}

// round 7
// speedup vs baseline: 2.1263x; 1.3054x over previous
#include <cuda_runtime.h>
#include <cuda_fp16.h>
#include <mma.h>
#include <cstdint>

using namespace nvcuda;

#define N_NODES_C 50000
#define N_PAIRS_C 800000
#define NHEADS_C 4
#define HEAD_DIM_C 64
#define NF_C 256   // NHEADS*HEAD_DIM
#define CAP 96
#define OVF_CAP 4096

// scratch (allocation-free rule: __device__ globals)
__device__ __half g_q[N_NODES_C * NF_C];
__device__ __half g_k[N_NODES_C * NF_C];
__device__ __half g_v[N_NODES_C * NF_C];
__device__ __half g_xh[(size_t)N_NODES_C * NF_C];         // fp16 x
__device__ __half g_wh[3 * NHEADS_C * HEAD_DIM_C * HEAD_DIM_C]; // fp16 W (q,k,v)
__device__ float  g_alpha[(size_t)N_PAIRS_C * NHEADS_C];

__device__ int   g_cnt[N_NODES_C];
__device__ int2  g_bkt[(size_t)N_NODES_C * CAP];
__device__ int   g_ovf_cnt;
__device__ int   g_ovf[OVF_CAP];

// ---------------------------------------------------------------------------
// Convert weights to fp16: g_wh[mat*16384 + h*4096 + e*64 + d]
// 49152 elems, 4 per thread -> 12288 threads = 48 blocks x 256
// ---------------------------------------------------------------------------
__global__ void conv_w_kernel(const float* __restrict__ Wq,
                              const float* __restrict__ Wk,
                              const float* __restrict__ Wv) {
    int t = blockIdx.x * blockDim.x + threadIdx.x;
    int base = t * 4;
    if (base >= 3 * 16384) return;
    int mat = base >> 14;
    int r   = base & 16383;
    const float* src = (mat == 0) ? Wq : ((mat == 1) ? Wk : Wv);
    float4 f = *(const float4*)(src + r);
    __half2 h0 = __floats2half2_rn(f.x, f.y);
    __half2 h1 = __floats2half2_rn(f.z, f.w);
    uint2 out;
    out.x = *(const unsigned*)&h0;
    out.y = *(const unsigned*)&h1;
    *(uint2*)(g_wh + mat * 16384 + r) = out;
}

// ---------------------------------------------------------------------------
// Convert x to fp16: 12.8M elems, 8 per thread -> 1.6M threads
// ---------------------------------------------------------------------------
__global__ void conv_x_kernel(const float* __restrict__ x) {
    size_t t = (size_t)blockIdx.x * blockDim.x + threadIdx.x;
    size_t base = t * 8;
    if (base >= (size_t)N_NODES_C * NF_C) return;
    float4 f0 = *(const float4*)(x + base);
    float4 f1 = *(const float4*)(x + base + 4);
    __half2 h0 = __floats2half2_rn(f0.x, f0.y);
    __half2 h1 = __floats2half2_rn(f0.z, f0.w);
    __half2 h2 = __floats2half2_rn(f1.x, f1.y);
    __half2 h3 = __floats2half2_rn(f1.z, f1.w);
    uint4 out;
    out.x = *(const unsigned*)&h0;
    out.y = *(const unsigned*)&h1;
    out.z = *(const unsigned*)&h2;
    out.w = *(const unsigned*)&h3;
    *(uint4*)(g_xh + base) = out;
}

// ---------------------------------------------------------------------------
// Tensor-core projection: warp per 16-node m-tile.
// Q[n,e] = sum_d X[n, h*64+d] * W[h,e,d]
//   A = x tile (row-major, lda=256), B = W (col-major in (d,e): elem at e*64+d)
// ---------------------------------------------------------------------------
#define PROJ_WARPS 8
__global__ void __launch_bounds__(PROJ_WARPS * 32)
proj_wmma_kernel() {
    __shared__ float sbuf[PROJ_WARPS][256];
    int warp = threadIdx.x >> 5;
    int lane = threadIdx.x & 31;
    int tile = blockIdx.x * PROJ_WARPS + warp;
    if (tile >= N_NODES_C / 16) return;   // 50000 % 16 == 0
    int n0 = tile * 16;

    const __half* A0 = g_xh + (size_t)n0 * NF_C;

    for (int h = 0; h < NHEADS_C; h++) {
        // hoist A fragments for this head (4 k-tiles of 16)
        wmma::fragment<wmma::matrix_a, 16, 16, 16, __half, wmma::row_major> a[4];
#pragma unroll
        for (int kt = 0; kt < 4; kt++)
            wmma::load_matrix_sync(a[kt], A0 + h * HEAD_DIM_C + kt * 16, NF_C);

        for (int mat = 0; mat < 3; mat++) {
            const __half* Wb = g_wh + (mat * NHEADS_C + h) * 4096;
            __half* out = (mat == 0) ? g_q : ((mat == 1) ? g_k : g_v);
#pragma unroll
            for (int et = 0; et < 4; et++) {
                wmma::fragment<wmma::accumulator, 16, 16, 16, float> c;
                wmma::fill_fragment(c, 0.0f);
#pragma unroll
                for (int kt = 0; kt < 4; kt++) {
                    wmma::fragment<wmma::matrix_b, 16, 16, 16, __half, wmma::col_major> b;
                    wmma::load_matrix_sync(b, Wb + et * 16 * 64 + kt * 16, 64);
                    wmma::mma_sync(c, a[kt], b, c);
                }
                wmma::store_matrix_sync(sbuf[warp], c, 16, wmma::mem_row_major);
                __syncwarp();
                // write 16x16 tile as fp16: lane -> (row = lane/2, 8 cols)
                int row = lane >> 1;
                int seg = lane & 1;
                const float* src = sbuf[warp] + row * 16 + seg * 8;
                __half2 o0 = __floats2half2_rn(src[0], src[1]);
                __half2 o1 = __floats2half2_rn(src[2], src[3]);
                __half2 o2 = __floats2half2_rn(src[4], src[5]);
                __half2 o3 = __floats2half2_rn(src[6], src[7]);
                uint4 pack;
                pack.x = *(const unsigned*)&o0;
                pack.y = *(const unsigned*)&o1;
                pack.z = *(const unsigned*)&o2;
                pack.w = *(const unsigned*)&o3;
                *(uint4*)(out + (size_t)(n0 + row) * NF_C + h * HEAD_DIM_C
                          + et * 16 + seg * 8) = pack;
                __syncwarp();
            }
        }
    }
}

// ---------------------------------------------------------------------------
// Bucket build
// ---------------------------------------------------------------------------
__global__ void zero_cnt_kernel() {
    int t = blockIdx.x * blockDim.x + threadIdx.x;
    if (t < N_NODES_C) g_cnt[t] = 0;
    if (t == 0) g_ovf_cnt = 0;
}

__global__ void bucket_kernel(const int* __restrict__ idx_i,
                              const int* __restrict__ idx_j) {
    int e = blockIdx.x * blockDim.x + threadIdx.x;
    if (e >= N_PAIRS_C) return;
    int i = idx_i[e];
    int pos = atomicAdd(&g_cnt[i], 1);
    if (pos < CAP) {
        g_bkt[(size_t)i * CAP + pos] = make_int2(e, idx_j[e]);
    } else {
        int p = atomicAdd(&g_ovf_cnt, 1);
        if (p < OVF_CAP) g_ovf[p] = e;
    }
}

// ---------------------------------------------------------------------------
// dot helper
// ---------------------------------------------------------------------------
__device__ __forceinline__ float dot8_h(uint4 qu, uint4 ku, float4 w0, float4 w1) {
    const __half2* q2 = (const __half2*)&qu;
    const __half2* k2 = (const __half2*)&ku;
    float2 qf0 = __half22float2(q2[0]);
    float2 qf1 = __half22float2(q2[1]);
    float2 qf2 = __half22float2(q2[2]);
    float2 qf3 = __half22float2(q2[3]);
    float2 kf0 = __half22float2(k2[0]);
    float2 kf1 = __half22float2(k2[1]);
    float2 kf2 = __half22float2(k2[2]);
    float2 kf3 = __half22float2(k2[3]);
    float s;
    s  = qf0.x * w0.x * kf0.x;
    s += qf0.y * w0.y * kf0.y;
    s += qf1.x * w0.z * kf1.x;
    s += qf1.y * w0.w * kf1.y;
    s += qf2.x * w1.x * kf2.x;
    s += qf2.y * w1.y * kf2.y;
    s += qf3.x * w1.z * kf3.x;
    s += qf3.y * w1.w * kf3.y;
    return s;
}

// ---------------------------------------------------------------------------
// Kernel A: alpha stream (unchanged)
// ---------------------------------------------------------------------------
__global__ void __launch_bounds__(256)
alpha_kernel(const float* __restrict__ w_ij,
             const int* __restrict__ idx_i,
             const int* __restrict__ idx_j,
             const float* __restrict__ phi) {
    int warp = (blockIdx.x * blockDim.x + threadIdx.x) >> 5;
    int lane = threadIdx.x & 31;
    int e0 = warp * 2;
    if (e0 >= N_PAIRS_C) return;
    int e1 = e0 + 1;
    int off = lane * 8;

    int   i0 = __ldg(&idx_i[e0]), i1 = __ldg(&idx_i[e1]);
    int   j0 = __ldg(&idx_j[e0]), j1 = __ldg(&idx_j[e1]);
    float p0 = __ldg(&phi[e0]),   p1 = __ldg(&phi[e1]);

    const float4* wp0 = (const float4*)(w_ij + (size_t)e0 * NF_C + off);
    const float4* wp1 = (const float4*)(w_ij + (size_t)e1 * NF_C + off);
    float4 w00 = __ldcs(wp0);
    float4 w01 = __ldcs(wp0 + 1);
    float4 w10 = __ldcs(wp1);
    float4 w11 = __ldcs(wp1 + 1);

    uint4 qu0 = __ldg((const uint4*)(g_q + (size_t)i0 * NF_C + off));
    uint4 ku0 = __ldg((const uint4*)(g_k + (size_t)j0 * NF_C + off));
    uint4 qu1 = __ldg((const uint4*)(g_q + (size_t)i1 * NF_C + off));
    uint4 ku1 = __ldg((const uint4*)(g_k + (size_t)j1 * NF_C + off));

    float s0 = dot8_h(qu0, ku0, w00, w01);
    float s1 = dot8_h(qu1, ku1, w10, w11);

    s0 += __shfl_xor_sync(0xffffffffu, s0, 1);
    s1 += __shfl_xor_sync(0xffffffffu, s1, 1);
    s0 += __shfl_xor_sync(0xffffffffu, s0, 2);
    s1 += __shfl_xor_sync(0xffffffffu, s1, 2);
    s0 += __shfl_xor_sync(0xffffffffu, s0, 4);
    s1 += __shfl_xor_sync(0xffffffffu, s1, 4);

    if ((lane & 7) == 0) {
        int h = lane >> 3;
        g_alpha[(size_t)e0 * NHEADS_C + h] = s0 * 0.125f * p0;
        g_alpha[(size_t)e1 * NHEADS_C + h] = s1 * 0.125f * p1;
    }
}

// ---------------------------------------------------------------------------
// Kernel B: gather-accumulate (unchanged)
// ---------------------------------------------------------------------------
__global__ void __launch_bounds__(256)
accum_kernel(float* __restrict__ y) {
    int node = (blockIdx.x * blockDim.x + threadIdx.x) >> 5;
    int lane = threadIdx.x & 31;
    if (node >= N_NODES_C) return;

    int deg = g_cnt[node];
    if (deg > CAP) deg = CAP;
    const size_t base = (size_t)node * CAP;
    const int off  = lane * 8;
    const int head = lane >> 3;

    float a0 = 0.f, a1 = 0.f, a2 = 0.f, a3 = 0.f;
    float a4 = 0.f, a5 = 0.f, a6 = 0.f, a7 = 0.f;

    int t = 0;
    for (; t + 2 <= deg; t += 2) {
        int2 m0 = g_bkt[base + t];
        int2 m1 = g_bkt[base + t + 1];
        float al0 = __ldg(&g_alpha[(size_t)m0.x * NHEADS_C + head]);
        float al1 = __ldg(&g_alpha[(size_t)m1.x * NHEADS_C + head]);
        uint4 vu0 = __ldg((const uint4*)(g_v + (size_t)m0.y * NF_C + off));
        uint4 vu1 = __ldg((const uint4*)(g_v + (size_t)m1.y * NF_C + off));

        const __half2* v20 = (const __half2*)&vu0;
        const __half2* v21 = (const __half2*)&vu1;
        float2 f;
        f = __half22float2(v20[0]); a0 = fmaf(al0, f.x, a0); a1 = fmaf(al0, f.y, a1);
        f = __half22float2(v20[1]); a2 = fmaf(al0, f.x, a2); a3 = fmaf(al0, f.y, a3);
        f = __half22float2(v20[2]); a4 = fmaf(al0, f.x, a4); a5 = fmaf(al0, f.y, a5);
        f = __half22float2(v20[3]); a6 = fmaf(al0, f.x, a6); a7 = fmaf(al0, f.y, a7);
        f = __half22float2(v21[0]); a0 = fmaf(al1, f.x, a0); a1 = fmaf(al1, f.y, a1);
        f = __half22float2(v21[1]); a2 = fmaf(al1, f.x, a2); a3 = fmaf(al1, f.y, a3);
        f = __half22float2(v21[2]); a4 = fmaf(al1, f.x, a4); a5 = fmaf(al1, f.y, a5);
        f = __half22float2(v21[3]); a6 = fmaf(al1, f.x, a6); a7 = fmaf(al1, f.y, a7);
    }
    if (t < deg) {
        int2 m0 = g_bkt[base + t];
        float al0 = __ldg(&g_alpha[(size_t)m0.x * NHEADS_C + head]);
        uint4 vu0 = __ldg((const uint4*)(g_v + (size_t)m0.y * NF_C + off));
        const __half2* v20 = (const __half2*)&vu0;
        float2 f;
        f = __half22float2(v20[0]); a0 = fmaf(al0, f.x, a0); a1 = fmaf(al0, f.y, a1);
        f = __half22float2(v20[1]); a2 = fmaf(al0, f.x, a2); a3 = fmaf(al0, f.y, a3);
        f = __half22float2(v20[2]); a4 = fmaf(al0, f.x, a4); a5 = fmaf(al0, f.y, a5);
        f = __half22float2(v20[3]); a6 = fmaf(al0, f.x, a6); a7 = fmaf(al0, f.y, a7);
    }

    float4* yp = (float4*)(y + (size_t)node * NF_C + off);
    yp[0] = make_float4(a0, a1, a2, a3);
    yp[1] = make_float4(a4, a5, a6, a7);
}

// ---------------------------------------------------------------------------
// Overflow fallback
// ---------------------------------------------------------------------------
__global__ void overflow_kernel(const int* __restrict__ idx_i,
                                const int* __restrict__ idx_j,
                                float* __restrict__ y) {
    int n = g_ovf_cnt;
    if (n > OVF_CAP) n = OVF_CAP;
    int lane = threadIdx.x & 31;
    for (int t = (int)(threadIdx.x >> 5); t < n; t += (int)(blockDim.x >> 5)) {
        int e = g_ovf[t];
        int i = idx_i[e];
        int j = idx_j[e];
        int off = lane * 8;
        int head = lane >> 3;

        float alpha = g_alpha[(size_t)e * NHEADS_C + head];
        uint4 vu = *(const uint4*)(g_v + (size_t)j * NF_C + off);
        const __half2* v2 = (const __half2*)&vu;
        float2 f0 = __half22float2(v2[0]);
        float2 f1 = __half22float2(v2[1]);
        float2 f2 = __half22float2(v2[2]);
        float2 f3 = __half22float2(v2[3]);
        float* yp = y + (size_t)i * NF_C + off;
        atomicAdd(yp + 0, alpha * f0.x);
        atomicAdd(yp + 1, alpha * f0.y);
        atomicAdd(yp + 2, alpha * f1.x);
        atomicAdd(yp + 3, alpha * f1.y);
        atomicAdd(yp + 4, alpha * f2.x);
        atomicAdd(yp + 5, alpha * f2.y);
        atomicAdd(yp + 6, alpha * f3.x);
        atomicAdd(yp + 7, alpha * f3.y);
    }
}

// ---------------------------------------------------------------------------
// launch
// ---------------------------------------------------------------------------
extern "C" void kernel_launch(void* const* d_in, const int* in_sizes, int n_in,
                              void* d_out, int out_size) {
    const float* x     = (const float*)d_in[0];
    const float* w_ij  = (const float*)d_in[1];
    const int*   idx_i = (const int*)d_in[2];
    const int*   idx_j = (const int*)d_in[3];
    const float* phi   = (const float*)d_in[4];
    const float* Wq    = (const float*)d_in[5];
    const float* Wk    = (const float*)d_in[6];
    const float* Wv    = (const float*)d_in[7];
    float* y = (float*)d_out;

    // fp16 conversions
    conv_w_kernel<<<48, 256>>>(Wq, Wk, Wv);
    conv_x_kernel<<<6250, 256>>>(x);

    // bucket build
    zero_cnt_kernel<<<(N_NODES_C + 255) / 256, 256>>>();
    bucket_kernel<<<(N_PAIRS_C + 255) / 256, 256>>>(idx_i, idx_j);

    // tensor-core projections: 3125 m-tiles / 8 warps per block
    int ptiles = N_NODES_C / 16;                   // 3125
    proj_wmma_kernel<<<(ptiles + PROJ_WARPS - 1) / PROJ_WARPS, PROJ_WARPS * 32>>>();

    // A: alpha stream
    int ablocks = (N_PAIRS_C + 15) / 16;
    alpha_kernel<<<ablocks, 256>>>(w_ij, idx_i, idx_j, phi);

    // B: gather-accumulate
    int nblocks = (N_NODES_C + 7) / 8;
    accum_kernel<<<nblocks, 256>>>(y);

    // overflow (usually empty)
    overflow_kernel<<<1, 256>>>(idx_i, idx_j, y);
}